// round 9
// baseline (speedup 1.0000x reference)
#include <cuda_runtime.h>
#include <cuda_bf16.h>
#include <cstdint>

#define HH 128
#define WW 128
#define HWP 16384      // HH*WW
#define CIN 256
#define OCH 256
#define BATCH 2
#define NPIX 32768     // BATCH*HWP
#define LDK 40         // padded k-stride for smem tiles

// -------- scratch (device globals) --------
__device__ __nv_bfloat16 g_xb[(size_t)NPIX * CIN];    // x in NHWC bf16
__device__ __nv_bfloat16 g_agg[(size_t)NPIX * CIN];   // aggregated samples NHWC bf16
__device__ float g_tmp[(size_t)BATCH * 27 * HWP];     // offset conv output (planar fp32)
__device__ __nv_bfloat16 g_w3[32 * 2304];             // offconv weights [o(pad32)][tap*256+c]
__device__ __nv_bfloat16 g_wproj[256 * 256];          // 1x1 weights bf16 [o][c]
__device__ float g_part[288];                         // partial sum-of-exp
__device__ float g_inv[18];                           // 1/sum(exp) per (b,k) mask plane

// ================= mma.sync bf16 m16n8k16 =================
__device__ __forceinline__ void mma16816(float* c, uint32_t a0, uint32_t a1,
                                         uint32_t a2, uint32_t a3,
                                         uint32_t b0, uint32_t b1) {
    asm volatile(
        "mma.sync.aligned.m16n8k16.row.col.f32.bf16.bf16.f32 "
        "{%0,%1,%2,%3}, {%4,%5,%6,%7}, {%8,%9}, {%0,%1,%2,%3};\n"
        : "+f"(c[0]), "+f"(c[1]), "+f"(c[2]), "+f"(c[3])
        : "r"(a0), "r"(a1), "r"(a2), "r"(a3), "r"(b0), "r"(b1));
}

// ================= K1: NCHW -> NHWC bf16 =================
__global__ void k_transpose(const float* __restrict__ x) {
    __shared__ float t[32][33];
    int p0 = blockIdx.x * 32;
    int c0 = blockIdx.y * 32;
    int b  = blockIdx.z;
    int tx = threadIdx.x, ty = threadIdx.y;
    int tid = ty * 32 + tx;
    const float* xb = x + (size_t)b * CIN * HWP;
#pragma unroll
    for (int i = 0; i < 32; i += 8)
        t[ty + i][tx] = xb[(size_t)(c0 + ty + i) * HWP + p0 + tx];
    __syncthreads();
    __nv_bfloat162* xn = (__nv_bfloat162*)(g_xb + (size_t)b * HWP * CIN);
#pragma unroll
    for (int pass = 0; pass < 2; ++pass) {
        int r  = (tid >> 4) + pass * 16;   // pixel row within tile
        int pc = tid & 15;                 // channel pair
        __nv_bfloat162 v = __floats2bfloat162_rn(t[2 * pc][r], t[2 * pc + 1][r]);
        xn[((size_t)(p0 + r) * CIN + c0) / 2 + pc] = v;
    }
}

// ================= K0: weight prep (both GEMMs) =================
__global__ void k_wprep(const float* __restrict__ w_off,
                        const float* __restrict__ weight) {
    int i = blockIdx.x * 256 + threadIdx.x;
    if (i < 32 * 2304) {
        int k = i % 2304, o = i / 2304;
        float v = 0.0f;
        if (o < 27) {
            int tap = k / 256, c = k % 256;
            v = w_off[(size_t)(o * 256 + c) * 9 + tap];
        }
        g_w3[i] = __float2bfloat16(v);
    } else {
        int j = i - 32 * 2304;
        if (j < 65536) g_wproj[j] = __float2bfloat16(weight[j]);
    }
}

// ================= K2: offset conv, implicit-GEMM bf16 mma (R7 version) =====
// One block = one image row (128 px). Double-buffered, 1 barrier/chunk.
__global__ __launch_bounds__(256) void k_offmma(const float* __restrict__ b_off) {
    __shared__ __nv_bfloat16 sA[2][32 * LDK];
    __shared__ __nv_bfloat16 sB[2][128 * LDK];
    int bid = blockIdx.x;               // 0..255
    int b = bid >> 7, y = bid & 127;
    int tid = threadIdx.x;
    int warp = tid >> 5, lane = tid & 31;
    int g = lane >> 2, tg = lane & 3;

    float acc[4][4] = {};

    int sxx = tid >> 1;                 // B stage: pixel x (0..127)
    int scc = (tid & 1) * 16;           // B stage: channel sub-offset
    int sm  = tid >> 3;                 // A stage: row (0..31)
    int skk = (tid & 7) * 4;            // A stage: k sub-offset

    uint2 ra;
    float4 rb0, rb1;
    auto load = [&](int chunk) {
        int tap = chunk >> 3;
        int c0  = (chunk & 7) * 32;
        int k0  = tap * 256 + c0;
        ra = *(const uint2*)(g_w3 + (size_t)sm * 2304 + k0 + skk);
        int yy = y + tap / 3 - 1;
        int sx = sxx + tap % 3 - 1;
        rb0 = make_float4(0.f, 0.f, 0.f, 0.f);
        rb1 = rb0;
        if (yy >= 0 && yy < HH && sx >= 0 && sx < WW) {
            const float4* src = (const float4*)(g_xb +
                ((size_t)((b << 14) + yy * WW + sx) * CIN + c0 + scc));
            rb0 = src[0];
            rb1 = src[1];
        }
    };
    auto store = [&](int buf) {
        *(uint2*)&sA[buf][sm * LDK + skk]       = ra;
        *(float4*)&sB[buf][sxx * LDK + scc]     = rb0;
        *(float4*)&sB[buf][sxx * LDK + scc + 8] = rb1;
    };

    load(0);
    store(0);
    __syncthreads();

    int n0 = warp * 16;
    for (int c = 0; c < 72; ++c) {
        int buf = c & 1;
        if (c < 71) load(c + 1);
#pragma unroll
        for (int ks = 0; ks < 2; ++ks) {
            int kk = ks * 16;
            uint32_t a[2][4];
#pragma unroll
            for (int mt = 0; mt < 2; ++mt) {
                int m = mt * 16;
                a[mt][0] = *(uint32_t*)&sA[buf][(m + g) * LDK + kk + tg * 2];
                a[mt][1] = *(uint32_t*)&sA[buf][(m + g + 8) * LDK + kk + tg * 2];
                a[mt][2] = *(uint32_t*)&sA[buf][(m + g) * LDK + kk + tg * 2 + 8];
                a[mt][3] = *(uint32_t*)&sA[buf][(m + g + 8) * LDK + kk + tg * 2 + 8];
            }
#pragma unroll
            for (int nt = 0; nt < 2; ++nt) {
                int n = n0 + nt * 8;
                uint32_t b0 = *(uint32_t*)&sB[buf][(n + g) * LDK + kk + tg * 2];
                uint32_t b1 = *(uint32_t*)&sB[buf][(n + g) * LDK + kk + tg * 2 + 8];
#pragma unroll
                for (int mt = 0; mt < 2; ++mt)
                    mma16816(acc[mt * 2 + nt], a[mt][0], a[mt][1], a[mt][2],
                             a[mt][3], b0, b1);
            }
        }
        if (c < 71) store(buf ^ 1);
        __syncthreads();
    }

    int p0 = y * WW + warp * 16;
    float* outb = g_tmp + (size_t)b * 27 * HWP;
#pragma unroll
    for (int mt = 0; mt < 2; ++mt)
#pragma unroll
        for (int nt = 0; nt < 2; ++nt) {
            float* c = acc[mt * 2 + nt];
            int col = p0 + nt * 8 + tg * 2;
            int o1 = mt * 16 + g, o2 = o1 + 8;
            if (o1 < 27) {
                float bo = b_off[o1];
                *(float2*)&outb[(size_t)o1 * HWP + col] =
                    make_float2(c[0] + bo, c[1] + bo);
            }
            if (o2 < 27) {
                float bo = b_off[o2];
                *(float2*)&outb[(size_t)o2 * HWP + col] =
                    make_float2(c[2] + bo, c[3] + bo);
            }
        }
}

// ================= K3a/K3b: two-stage sum-of-exp per mask plane =============
__global__ __launch_bounds__(256) void k_sumexp1() {
    int blk = blockIdx.x;               // 0..287
    int bi = blk >> 4, sl = blk & 15;
    const float* plane =
        g_tmp + (size_t)((bi / 9) * 27 + 18 + (bi % 9)) * HWP + sl * 1024;
    __shared__ float red[256];
    int tid = threadIdx.x;
    float s = expf(plane[tid]) + expf(plane[tid + 256]) +
              expf(plane[tid + 512]) + expf(plane[tid + 768]);
    red[tid] = s;
    __syncthreads();
    for (int st = 128; st > 0; st >>= 1) {
        if (tid < st) red[tid] += red[tid + st];
        __syncthreads();
    }
    if (tid == 0) g_part[blk] = red[0];
}

__global__ void k_sumexp2() {
    int i = threadIdx.x;
    if (i < 18) {
        float s = 0.0f;
#pragma unroll
        for (int j = 0; j < 16; ++j) s += g_part[i * 16 + j];
        g_inv[i] = 1.0f / s;
    }
}

// ================= K4: tiled bilinear gather =================
// Block = 8x8 pixel tile. 14x14 halo of x staged in smem (two 128-ch passes).
// Corners outside the halo (|offset|>~2, P~1e-5) go to an overflow list with
// global fallback. LDS-bound instead of L2-bound.
#define GSM_X     0                      // bf16[196*128]            (50176 B)
#define GSM_LOC   50176                  // int16[64*36]             ( 4608 B)
#define GSM_WT    54784                  // uint32[64*36]            ( 9216 B)
#define GSM_OVPL  64000                  // int[128]
#define GSM_OVOFF 64512                  // int[128]
#define GSM_OVW   65024                  // uint32[128]
#define GSM_NOV   65536                  // int
#define GSM_TOTAL 65600

__global__ __launch_bounds__(512) void k_gather() {
    extern __shared__ char sm[];
    __nv_bfloat16* s_x   = (__nv_bfloat16*)(sm + GSM_X);
    int16_t*       s_loc = (int16_t*)(sm + GSM_LOC);
    uint32_t*      s_wt  = (uint32_t*)(sm + GSM_WT);
    int*           s_ovpl  = (int*)(sm + GSM_OVPL);
    int*           s_ovoff = (int*)(sm + GSM_OVOFF);
    uint32_t*      s_ovw   = (uint32_t*)(sm + GSM_OVW);
    int*           s_nov   = (int*)(sm + GSM_NOV);

    int tx0 = blockIdx.x * 8;
    int ty0 = blockIdx.y * 8;
    int b   = blockIdx.z;
    int tid = threadIdx.x;

    if (tid == 0) *s_nov = 0;
    __syncthreads();

    // ---- per-pixel corner setup: one thread per (pixel, tap) ----
    auto setup_tap = [&](int pl, int k) {
        int py0 = pl >> 3, px0 = pl & 7;
        int y = ty0 + py0, xx = tx0 + px0;
        int p = y * WW + xx;
        size_t tb = (size_t)b * 27 * HWP + p;
        float dy = g_tmp[tb + (size_t)(2 * k) * HWP];
        float dx = g_tmp[tb + (size_t)(2 * k + 1) * HWP];
        float mv = g_tmp[tb + (size_t)(18 + k) * HWP];
        float m  = expf(mv) * g_inv[b * 9 + k];
        float py = dy + (float)(k / 3 - 1 + y);
        float px = dx + (float)(k % 3 - 1 + xx);
        float fy = floorf(py), fx = floorf(px);
        int iy = (int)fy, ix = (int)fx;
        float ly = py - fy, lx = px - fx;
        float w[4];
        w[0] = (1.0f - ly) * (1.0f - lx) * m;
        w[1] = (1.0f - ly) * lx * m;
        w[2] = ly * (1.0f - lx) * m;
        w[3] = ly * lx * m;
        int base = pl * 36 + k * 4;
#pragma unroll
        for (int j = 0; j < 4; ++j) {
            int yc = iy + (j >> 1);
            int xc = ix + (j & 1);
            int loc = 0;
            float wv = 0.0f;
            if (yc >= 0 && yc < HH && xc >= 0 && xc < WW) {
                int cy = yc - (ty0 - 3), cx = xc - (tx0 - 3);
                if ((unsigned)cy < 14u && (unsigned)cx < 14u) {
                    loc = cy * 14 + cx;
                    wv = w[j];
                } else {  // rare: offset beyond halo -> overflow list
                    int e = atomicAdd(s_nov, 1);
                    if (e < 128) {
                        s_ovpl[e] = pl;
                        s_ovoff[e] = ((b << 14) + yc * WW + xc) * CIN;
                        __nv_bfloat162 h = __float2bfloat162_rn(w[j]);
                        s_ovw[e] = *(uint32_t*)&h;
                    }
                }
            }
            s_loc[base + j] = (int16_t)loc;
            __nv_bfloat162 h = __float2bfloat162_rn(wv);
            s_wt[base + j] = *(uint32_t*)&h;
        }
    };
    setup_tap(tid & 63, tid >> 6);      // taps 0..7 for all 64 pixels
    if (tid < 64) setup_tap(tid, 8);    // tap 8

    int pl = tid >> 3;
    int c16 = (tid & 7) * 16;           // channel offset within 128-ch half
    int py0 = pl >> 3, px0 = pl & 7;
    size_t nglob = (size_t)((b << 14) + (ty0 + py0) * WW + tx0 + px0);

#pragma unroll
    for (int half = 0; half < 2; ++half) {
        // ---- stage halo: 196 locations x 128 channels ----
        for (int i = tid; i < 196 * 16; i += 512) {
            int loc = i >> 4, v = i & 15;
            int cy = loc / 14, cx = loc - cy * 14;
            int yy = ty0 - 3 + cy, xw = tx0 - 3 + cx;
            float4 val = make_float4(0.f, 0.f, 0.f, 0.f);
            if (yy >= 0 && yy < HH && xw >= 0 && xw < WW)
                val = *(const float4*)(g_xb +
                    (size_t)((b << 14) + yy * WW + xw) * CIN + half * 128 + v * 8);
            *(float4*)&s_x[loc * 128 + v * 8] = val;
        }
        __syncthreads();

        // ---- accumulate 36 corners from smem ----
        __nv_bfloat162 z = __float2bfloat162_rn(0.0f);
        __nv_bfloat162 acc[8] = {z, z, z, z, z, z, z, z};
        int base = pl * 36;
#pragma unroll 6
        for (int t = 0; t < 36; ++t) {
            int loc = s_loc[base + t];
            uint32_t wb = s_wt[base + t];
            __nv_bfloat162 w2 = *(__nv_bfloat162*)&wb;
            const float4* xp = (const float4*)&s_x[loc * 128 + c16];
            float4 r0 = xp[0], r1 = xp[1];
            __nv_bfloat162* h0 = (__nv_bfloat162*)&r0;
            __nv_bfloat162* h1 = (__nv_bfloat162*)&r1;
#pragma unroll
            for (int q = 0; q < 4; ++q) {
                acc[q]     = __hfma2(h0[q], w2, acc[q]);
                acc[4 + q] = __hfma2(h1[q], w2, acc[4 + q]);
            }
        }
        // ---- overflow corners (global fallback; normally zero entries) ----
        int nov = *s_nov;
        if (nov > 128) nov = 128;
        for (int e = 0; e < nov; ++e) {
            if (s_ovpl[e] == pl) {
                uint32_t wb = s_ovw[e];
                __nv_bfloat162 w2 = *(__nv_bfloat162*)&wb;
                const float4* xp = (const float4*)(g_xb + s_ovoff[e] +
                                                   half * 128 + c16);
                float4 r0 = xp[0], r1 = xp[1];
                __nv_bfloat162* h0 = (__nv_bfloat162*)&r0;
                __nv_bfloat162* h1 = (__nv_bfloat162*)&r1;
#pragma unroll
                for (int q = 0; q < 4; ++q) {
                    acc[q]     = __hfma2(h0[q], w2, acc[q]);
                    acc[4 + q] = __hfma2(h1[q], w2, acc[4 + q]);
                }
            }
        }
        // ---- write 16 channels ----
        float4* dst = (float4*)(g_agg + nglob * CIN + half * 128 + c16);
        dst[0] = *(float4*)&acc[0];
        dst[1] = *(float4*)&acc[4];
        __syncthreads();   // before next half overwrites s_x
    }
}

// ================= K5: 1x1 projection GEMM (bf16 mma) + bias, pipelined =====
__global__ __launch_bounds__(256) void k_projmma(const float* __restrict__ bias,
                                                 float* __restrict__ out) {
    __shared__ __nv_bfloat16 sA[2][128 * LDK];
    __shared__ __nv_bfloat16 sB[2][128 * LDK];
    int m0 = blockIdx.y * 128;
    int n0 = blockIdx.x * 128;
    int tid = threadIdx.x;
    int warp = tid >> 5, lane = tid & 31;
    int g = lane >> 2, tg = lane & 3;
    int wm = (warp >> 1) * 32;
    int wn = (warp & 1) * 64;

    float acc[2][8][4] = {};

    int sr = tid >> 1;
    int sk = (tid & 1) * 16;

    float4 ra0, ra1, rb0, rb1;
    auto load = [&](int chunk) {
        int k0 = chunk * 32;
        const float4* srcA =
            (const float4*)(g_wproj + (size_t)(m0 + sr) * 256 + k0 + sk);
        ra0 = srcA[0];
        ra1 = srcA[1];
        const float4* srcB =
            (const float4*)(g_agg + (size_t)(n0 + sr) * 256 + k0 + sk);
        rb0 = srcB[0];
        rb1 = srcB[1];
    };
    auto store = [&](int buf) {
        *(float4*)&sA[buf][sr * LDK + sk]     = ra0;
        *(float4*)&sA[buf][sr * LDK + sk + 8] = ra1;
        *(float4*)&sB[buf][sr * LDK + sk]     = rb0;
        *(float4*)&sB[buf][sr * LDK + sk + 8] = rb1;
    };

    load(0);
    store(0);
    __syncthreads();

    for (int c = 0; c < 8; ++c) {
        int buf = c & 1;
        if (c < 7) load(c + 1);
#pragma unroll
        for (int ks = 0; ks < 2; ++ks) {
            int kk = ks * 16;
            uint32_t a[2][4];
#pragma unroll
            for (int mt = 0; mt < 2; ++mt) {
                int m = wm + mt * 16;
                a[mt][0] = *(uint32_t*)&sA[buf][(m + g) * LDK + kk + tg * 2];
                a[mt][1] = *(uint32_t*)&sA[buf][(m + g + 8) * LDK + kk + tg * 2];
                a[mt][2] = *(uint32_t*)&sA[buf][(m + g) * LDK + kk + tg * 2 + 8];
                a[mt][3] = *(uint32_t*)&sA[buf][(m + g + 8) * LDK + kk + tg * 2 + 8];
            }
#pragma unroll
            for (int nt = 0; nt < 8; ++nt) {
                int n = wn + nt * 8;
                uint32_t b0 = *(uint32_t*)&sB[buf][(n + g) * LDK + kk + tg * 2];
                uint32_t b1 = *(uint32_t*)&sB[buf][(n + g) * LDK + kk + tg * 2 + 8];
#pragma unroll
                for (int mt = 0; mt < 2; ++mt)
                    mma16816(acc[mt][nt], a[mt][0], a[mt][1], a[mt][2], a[mt][3],
                             b0, b1);
            }
        }
        if (c < 7) store(buf ^ 1);
        __syncthreads();
    }

    int b = n0 >> 14;
    int p0 = (n0 & (HWP - 1)) + wn;
#pragma unroll
    for (int mt = 0; mt < 2; ++mt) {
        int o1 = m0 + wm + mt * 16 + g;
        int o2 = o1 + 8;
        float bo1 = bias[o1], bo2 = bias[o2];
        float* r1 = out + (size_t)(b * OCH + o1) * HWP + p0;
        float* r2 = out + (size_t)(b * OCH + o2) * HWP + p0;
#pragma unroll
        for (int nt = 0; nt < 8; ++nt) {
            float* c = acc[mt][nt];
            int col = nt * 8 + tg * 2;
            *(float2*)&r1[col] = make_float2(c[0] + bo1, c[1] + bo1);
            *(float2*)&r2[col] = make_float2(c[2] + bo2, c[3] + bo2);
        }
    }
}

// ================= launch =================
extern "C" void kernel_launch(void* const* d_in, const int* in_sizes, int n_in,
                              void* d_out, int out_size) {
    const float* x      = (const float*)d_in[0];
    const float* w_off  = (const float*)d_in[1];
    const float* b_off  = (const float*)d_in[2];
    const float* weight = (const float*)d_in[3];
    const float* bias   = (const float*)d_in[4];
    float* out = (float*)d_out;

    cudaFuncSetAttribute(k_gather, cudaFuncAttributeMaxDynamicSharedMemorySize,
                         GSM_TOTAL);

    k_transpose<<<dim3(HWP / 32, CIN / 32, BATCH), dim3(32, 8)>>>(x);
    k_wprep<<<544, 256>>>(w_off, weight);
    k_offmma<<<256, 256>>>(b_off);
    k_sumexp1<<<288, 256>>>();
    k_sumexp2<<<1, 32>>>();
    k_gather<<<dim3(16, 16, BATCH), 512, GSM_TOTAL>>>();
    k_projmma<<<dim3(NPIX / 128, OCH / 128), 256>>>(bias, out);
}

// round 11
// speedup vs baseline: 1.0751x; 1.0751x over previous
#include <cuda_runtime.h>
#include <cuda_bf16.h>
#include <cstdint>

#define HH 128
#define WW 128
#define HWP 16384      // HH*WW
#define CIN 256
#define OCH 256
#define BATCH 2
#define NPIX 32768     // BATCH*HWP
#define LDK 40         // padded k-stride for smem tiles

// -------- scratch (device globals) --------
__device__ __nv_bfloat16 g_xb[(size_t)NPIX * CIN];    // x in NHWC bf16
__device__ __nv_bfloat16 g_agg[(size_t)NPIX * CIN];   // aggregated samples NHWC bf16
__device__ float g_tmp[(size_t)BATCH * 27 * HWP];     // offset conv output (planar fp32)
__device__ __nv_bfloat16 g_w3[32 * 2304];             // offconv weights [o(pad32)][tap*256+c]
__device__ __nv_bfloat16 g_wproj[256 * 256];          // 1x1 weights bf16 [o][c]
__device__ float g_part[288];                         // partial sum-of-exp

// ================= mma.sync bf16 m16n8k16 =================
__device__ __forceinline__ void mma16816(float* c, uint32_t a0, uint32_t a1,
                                         uint32_t a2, uint32_t a3,
                                         uint32_t b0, uint32_t b1) {
    asm volatile(
        "mma.sync.aligned.m16n8k16.row.col.f32.bf16.bf16.f32 "
        "{%0,%1,%2,%3}, {%4,%5,%6,%7}, {%8,%9}, {%0,%1,%2,%3};\n"
        : "+f"(c[0]), "+f"(c[1]), "+f"(c[2]), "+f"(c[3])
        : "r"(a0), "r"(a1), "r"(a2), "r"(a3), "r"(b0), "r"(b1));
}

// ================= K0: fused NCHW->NHWC transpose + weight prep =============
// blockIdx.z < 2 : transpose batch z;  blockIdx.z == 2 : weight prep
__global__ void k_prep(const float* __restrict__ x,
                       const float* __restrict__ w_off,
                       const float* __restrict__ weight) {
    int tx = threadIdx.x, ty = threadIdx.y;
    int ltid = ty * 32 + tx;
    if (blockIdx.z < 2) {
        __shared__ float t[32][33];
        int p0 = blockIdx.x * 32;
        int c0 = blockIdx.y * 32;
        int b  = blockIdx.z;
        const float* xb = x + (size_t)b * CIN * HWP;
#pragma unroll
        for (int i = 0; i < 32; i += 8)
            t[ty + i][tx] = xb[(size_t)(c0 + ty + i) * HWP + p0 + tx];
        __syncthreads();
        __nv_bfloat162* xn = (__nv_bfloat162*)(g_xb + (size_t)b * HWP * CIN);
#pragma unroll
        for (int pass = 0; pass < 2; ++pass) {
            int r  = (ltid >> 4) + pass * 16;
            int pc = ltid & 15;
            __nv_bfloat162 v =
                __floats2bfloat162_rn(t[2 * pc][r], t[2 * pc + 1][r]);
            xn[((size_t)(p0 + r) * CIN + c0) / 2 + pc] = v;
        }
    } else {
        int blk = blockIdx.x * 8 + blockIdx.y;   // 0..4095, use first 544
        if (blk >= 544) return;
        int i = blk * 256 + ltid;
        if (i < 32 * 2304) {
            int k = i % 2304, o = i / 2304;
            float v = 0.0f;
            if (o < 27) {
                int tap = k / 256, c = k % 256;
                v = w_off[(size_t)(o * 256 + c) * 9 + tap];
            }
            g_w3[i] = __float2bfloat16(v);
        } else {
            int j = i - 32 * 2304;
            if (j < 65536) g_wproj[j] = __float2bfloat16(weight[j]);
        }
    }
}

// ================= K2: offset conv, implicit-GEMM bf16 mma (R7 version) =====
// One block = one image row (128 px). Double-buffered, 1 barrier/chunk.
__global__ __launch_bounds__(256) void k_offmma(const float* __restrict__ b_off) {
    __shared__ __nv_bfloat16 sA[2][32 * LDK];
    __shared__ __nv_bfloat16 sB[2][128 * LDK];
    int bid = blockIdx.x;               // 0..255
    int b = bid >> 7, y = bid & 127;
    int tid = threadIdx.x;
    int warp = tid >> 5, lane = tid & 31;
    int g = lane >> 2, tg = lane & 3;

    float acc[4][4] = {};

    int sxx = tid >> 1;                 // B stage: pixel x (0..127)
    int scc = (tid & 1) * 16;           // B stage: channel sub-offset
    int sm  = tid >> 3;                 // A stage: row (0..31)
    int skk = (tid & 7) * 4;            // A stage: k sub-offset

    uint2 ra;
    float4 rb0, rb1;
    auto load = [&](int chunk) {
        int tap = chunk >> 3;
        int c0  = (chunk & 7) * 32;
        int k0  = tap * 256 + c0;
        ra = *(const uint2*)(g_w3 + (size_t)sm * 2304 + k0 + skk);
        int yy = y + tap / 3 - 1;
        int sx = sxx + tap % 3 - 1;
        rb0 = make_float4(0.f, 0.f, 0.f, 0.f);
        rb1 = rb0;
        if (yy >= 0 && yy < HH && sx >= 0 && sx < WW) {
            const float4* src = (const float4*)(g_xb +
                ((size_t)((b << 14) + yy * WW + sx) * CIN + c0 + scc));
            rb0 = src[0];
            rb1 = src[1];
        }
    };
    auto store = [&](int buf) {
        *(uint2*)&sA[buf][sm * LDK + skk]       = ra;
        *(float4*)&sB[buf][sxx * LDK + scc]     = rb0;
        *(float4*)&sB[buf][sxx * LDK + scc + 8] = rb1;
    };

    load(0);
    store(0);
    __syncthreads();

    int n0 = warp * 16;
    for (int c = 0; c < 72; ++c) {
        int buf = c & 1;
        if (c < 71) load(c + 1);
#pragma unroll
        for (int ks = 0; ks < 2; ++ks) {
            int kk = ks * 16;
            uint32_t a[2][4];
#pragma unroll
            for (int mt = 0; mt < 2; ++mt) {
                int m = mt * 16;
                a[mt][0] = *(uint32_t*)&sA[buf][(m + g) * LDK + kk + tg * 2];
                a[mt][1] = *(uint32_t*)&sA[buf][(m + g + 8) * LDK + kk + tg * 2];
                a[mt][2] = *(uint32_t*)&sA[buf][(m + g) * LDK + kk + tg * 2 + 8];
                a[mt][3] = *(uint32_t*)&sA[buf][(m + g + 8) * LDK + kk + tg * 2 + 8];
            }
#pragma unroll
            for (int nt = 0; nt < 2; ++nt) {
                int n = n0 + nt * 8;
                uint32_t b0 = *(uint32_t*)&sB[buf][(n + g) * LDK + kk + tg * 2];
                uint32_t b1 = *(uint32_t*)&sB[buf][(n + g) * LDK + kk + tg * 2 + 8];
#pragma unroll
                for (int mt = 0; mt < 2; ++mt)
                    mma16816(acc[mt * 2 + nt], a[mt][0], a[mt][1], a[mt][2],
                             a[mt][3], b0, b1);
            }
        }
        if (c < 71) store(buf ^ 1);
        __syncthreads();
    }

    int p0 = y * WW + warp * 16;
    float* outb = g_tmp + (size_t)b * 27 * HWP;
#pragma unroll
    for (int mt = 0; mt < 2; ++mt)
#pragma unroll
        for (int nt = 0; nt < 2; ++nt) {
            float* c = acc[mt * 2 + nt];
            int col = p0 + nt * 8 + tg * 2;
            int o1 = mt * 16 + g, o2 = o1 + 8;
            if (o1 < 27) {
                float bo = b_off[o1];
                *(float2*)&outb[(size_t)o1 * HWP + col] =
                    make_float2(c[0] + bo, c[1] + bo);
            }
            if (o2 < 27) {
                float bo = b_off[o2];
                *(float2*)&outb[(size_t)o2 * HWP + col] =
                    make_float2(c[2] + bo, c[3] + bo);
            }
        }
}

// ================= K3: stage-1 sum-of-exp per mask plane ====================
__global__ __launch_bounds__(256) void k_sumexp1() {
    int blk = blockIdx.x;               // 0..287
    int bi = blk >> 4, sl = blk & 15;
    const float* plane =
        g_tmp + (size_t)((bi / 9) * 27 + 18 + (bi % 9)) * HWP + sl * 1024;
    __shared__ float red[256];
    int tid = threadIdx.x;
    float s = expf(plane[tid]) + expf(plane[tid + 256]) +
              expf(plane[tid + 512]) + expf(plane[tid + 768]);
    red[tid] = s;
    __syncthreads();
    for (int st = 128; st > 0; st >>= 1) {
        if (tid < st) red[tid] += red[tid + st];
        __syncthreads();
    }
    if (tid == 0) g_part[blk] = red[0];
}

// ================= K4: bilinear gather + mask + sum over K (R7 flat) ========
// Prologue folds sum-exp stage 2 (18 sums of 16 partials) into smem.
// block = 16 pixels, 512 threads; 144 threads precompute corners;
// then 32 threads/pixel, 8 channels each, fp32 accumulation.
__global__ __launch_bounds__(512) void k_gather() {
    __shared__ int   s_off[576];
    __shared__ float s_w[576];
    __shared__ float s_inv[18];
    int base = blockIdx.x * 16;
    int tid = threadIdx.x;

    if (tid < 18) {
        float s = 0.0f;
#pragma unroll
        for (int j = 0; j < 16; ++j) s += g_part[tid * 16 + j];
        s_inv[tid] = 1.0f / s;
    }
    __syncthreads();

    if (tid < 144) {
        int pl = tid / 9, k = tid % 9;
        int n = base + pl;
        int b = n >> 14;
        int p = n & (HWP - 1);
        int y = p >> 7;
        int xx = p & (WW - 1);
        size_t tb = (size_t)b * 27 * HWP + p;
        float dy = g_tmp[tb + (size_t)(2 * k) * HWP];
        float dx = g_tmp[tb + (size_t)(2 * k + 1) * HWP];
        float mv = g_tmp[tb + (size_t)(18 + k) * HWP];
        float m  = expf(mv) * s_inv[b * 9 + k];
        float py = dy + (float)(k / 3 - 1 + y);
        float px = dx + (float)(k % 3 - 1 + xx);
        float fy = floorf(py), fx = floorf(px);
        int iy = (int)fy, ix = (int)fx;
        float ly = py - fy, lx = px - fx;
        float w[4];
        w[0] = (1.0f - ly) * (1.0f - lx) * m;
        w[1] = (1.0f - ly) * lx * m;
        w[2] = ly * (1.0f - lx) * m;
        w[3] = ly * lx * m;
        int idx = tid * 4;
#pragma unroll
        for (int j = 0; j < 4; ++j) {
            int yc = iy + (j >> 1);
            int xc = ix + (j & 1);
            bool v = (yc >= 0) && (yc < HH) && (xc >= 0) && (xc < WW);
            s_off[idx + j] = v ? (int)(((b << 14) + yc * WW + xc) * CIN) : -1;
            s_w[idx + j] = w[j];
        }
    }
    __syncthreads();

    int pl = tid >> 5;
    int c8 = (tid & 31) * 8;
    float acc[8] = {};
    int sb = pl * 36;
#pragma unroll
    for (int t = 0; t < 36; ++t) {
        int off = s_off[sb + t];
        if (off >= 0) {
            float w = s_w[sb + t];
            float4 raw = *(const float4*)(g_xb + off + c8);
            __nv_bfloat162* h = (__nv_bfloat162*)&raw;
#pragma unroll
            for (int q = 0; q < 4; ++q) {
                float2 f = __bfloat1622float2(h[q]);
                acc[2 * q]     += w * f.x;
                acc[2 * q + 1] += w * f.y;
            }
        }
    }
    int n = base + pl;
    __nv_bfloat162 outv[4];
#pragma unroll
    for (int q = 0; q < 4; ++q)
        outv[q] = __float22bfloat162_rn(make_float2(acc[2 * q], acc[2 * q + 1]));
    *(float4*)(g_agg + (size_t)n * CIN + c8) = *(float4*)outv;
}

// ================= K5: 1x1 projection GEMM (bf16 mma) + bias, pipelined =====
__global__ __launch_bounds__(256) void k_projmma(const float* __restrict__ bias,
                                                 float* __restrict__ out) {
    __shared__ __nv_bfloat16 sA[2][128 * LDK];
    __shared__ __nv_bfloat16 sB[2][128 * LDK];
    int m0 = blockIdx.y * 128;
    int n0 = blockIdx.x * 128;
    int tid = threadIdx.x;
    int warp = tid >> 5, lane = tid & 31;
    int g = lane >> 2, tg = lane & 3;
    int wm = (warp >> 1) * 32;
    int wn = (warp & 1) * 64;

    float acc[2][8][4] = {};

    int sr = tid >> 1;
    int sk = (tid & 1) * 16;

    float4 ra0, ra1, rb0, rb1;
    auto load = [&](int chunk) {
        int k0 = chunk * 32;
        const float4* srcA =
            (const float4*)(g_wproj + (size_t)(m0 + sr) * 256 + k0 + sk);
        ra0 = srcA[0];
        ra1 = srcA[1];
        const float4* srcB =
            (const float4*)(g_agg + (size_t)(n0 + sr) * 256 + k0 + sk);
        rb0 = srcB[0];
        rb1 = srcB[1];
    };
    auto store = [&](int buf) {
        *(float4*)&sA[buf][sr * LDK + sk]     = ra0;
        *(float4*)&sA[buf][sr * LDK + sk + 8] = ra1;
        *(float4*)&sB[buf][sr * LDK + sk]     = rb0;
        *(float4*)&sB[buf][sr * LDK + sk + 8] = rb1;
    };

    load(0);
    store(0);
    __syncthreads();

    for (int c = 0; c < 8; ++c) {
        int buf = c & 1;
        if (c < 7) load(c + 1);
#pragma unroll
        for (int ks = 0; ks < 2; ++ks) {
            int kk = ks * 16;
            uint32_t a[2][4];
#pragma unroll
            for (int mt = 0; mt < 2; ++mt) {
                int m = wm + mt * 16;
                a[mt][0] = *(uint32_t*)&sA[buf][(m + g) * LDK + kk + tg * 2];
                a[mt][1] = *(uint32_t*)&sA[buf][(m + g + 8) * LDK + kk + tg * 2];
                a[mt][2] = *(uint32_t*)&sA[buf][(m + g) * LDK + kk + tg * 2 + 8];
                a[mt][3] = *(uint32_t*)&sA[buf][(m + g + 8) * LDK + kk + tg * 2 + 8];
            }
#pragma unroll
            for (int nt = 0; nt < 8; ++nt) {
                int n = wn + nt * 8;
                uint32_t b0 = *(uint32_t*)&sB[buf][(n + g) * LDK + kk + tg * 2];
                uint32_t b1 = *(uint32_t*)&sB[buf][(n + g) * LDK + kk + tg * 2 + 8];
#pragma unroll
                for (int mt = 0; mt < 2; ++mt)
                    mma16816(acc[mt][nt], a[mt][0], a[mt][1], a[mt][2], a[mt][3],
                             b0, b1);
            }
        }
        if (c < 7) store(buf ^ 1);
        __syncthreads();
    }

    int b = n0 >> 14;
    int p0 = (n0 & (HWP - 1)) + wn;
#pragma unroll
    for (int mt = 0; mt < 2; ++mt) {
        int o1 = m0 + wm + mt * 16 + g;
        int o2 = o1 + 8;
        float bo1 = bias[o1], bo2 = bias[o2];
        float* r1 = out + (size_t)(b * OCH + o1) * HWP + p0;
        float* r2 = out + (size_t)(b * OCH + o2) * HWP + p0;
#pragma unroll
        for (int nt = 0; nt < 8; ++nt) {
            float* c = acc[mt][nt];
            int col = nt * 8 + tg * 2;
            *(float2*)&r1[col] = make_float2(c[0] + bo1, c[1] + bo1);
            *(float2*)&r2[col] = make_float2(c[2] + bo2, c[3] + bo2);
        }
    }
}

// ================= launch =================
// 5 launches; ncu profiles launch index 3 -> k_gather this round.
extern "C" void kernel_launch(void* const* d_in, const int* in_sizes, int n_in,
                              void* d_out, int out_size) {
    const float* x      = (const float*)d_in[0];
    const float* w_off  = (const float*)d_in[1];
    const float* b_off  = (const float*)d_in[2];
    const float* weight = (const float*)d_in[3];
    const float* bias   = (const float*)d_in[4];
    float* out = (float*)d_out;

    k_prep<<<dim3(HWP / 32, CIN / 32, 3), dim3(32, 8)>>>(x, w_off, weight);
    k_offmma<<<256, 256>>>(b_off);
    k_sumexp1<<<288, 256>>>();
    k_gather<<<NPIX / 16, 512>>>();
    k_projmma<<<dim3(NPIX / 128, OCH / 128), 256>>>(bias, out);
}

// round 13
// speedup vs baseline: 1.1415x; 1.0618x over previous
#include <cuda_runtime.h>
#include <cuda_bf16.h>
#include <cstdint>

#define HH 128
#define WW 128
#define HWP 16384      // HH*WW
#define CIN 256
#define OCH 256
#define BATCH 2
#define NPIX 32768     // BATCH*HWP
#define LDK 40         // padded k-stride for smem tiles

// -------- scratch (device globals) --------
__device__ __nv_bfloat16 g_xb[(size_t)NPIX * CIN];    // x in NHWC bf16
__device__ __nv_bfloat16 g_agg[(size_t)NPIX * CIN];   // aggregated samples NHWC bf16
__device__ float g_tmp[(size_t)BATCH * 27 * HWP];     // offset conv output (planar fp32)
__device__ __nv_bfloat16 g_w3[32 * 2304];             // offconv weights [o(pad32)][tap*256+c]
__device__ __nv_bfloat16 g_wproj[256 * 256];          // 1x1 weights bf16 [o][c]
__device__ float g_part[288];                         // partial sum-of-exp

// ================= mma.sync bf16 m16n8k16 =================
__device__ __forceinline__ void mma16816(float* c, uint32_t a0, uint32_t a1,
                                         uint32_t a2, uint32_t a3,
                                         uint32_t b0, uint32_t b1) {
    asm volatile(
        "mma.sync.aligned.m16n8k16.row.col.f32.bf16.bf16.f32 "
        "{%0,%1,%2,%3}, {%4,%5,%6,%7}, {%8,%9}, {%0,%1,%2,%3};\n"
        : "+f"(c[0]), "+f"(c[1]), "+f"(c[2]), "+f"(c[3])
        : "r"(a0), "r"(a1), "r"(a2), "r"(a3), "r"(b0), "r"(b1));
}

// ================= K1: NCHW -> NHWC bf16 (one batch per launch) =============
__global__ void k_transpose(const float* __restrict__ x, int b) {
    __shared__ float t[32][33];
    int p0 = blockIdx.x * 32;
    int c0 = blockIdx.y * 32;
    int tx = threadIdx.x, ty = threadIdx.y;
    int tid = ty * 32 + tx;
    const float* xb = x + (size_t)b * CIN * HWP;
#pragma unroll
    for (int i = 0; i < 32; i += 8)
        t[ty + i][tx] = xb[(size_t)(c0 + ty + i) * HWP + p0 + tx];
    __syncthreads();
    __nv_bfloat162* xn = (__nv_bfloat162*)(g_xb + (size_t)b * HWP * CIN);
#pragma unroll
    for (int pass = 0; pass < 2; ++pass) {
        int r  = (tid >> 4) + pass * 16;
        int pc = tid & 15;
        __nv_bfloat162 v = __floats2bfloat162_rn(t[2 * pc][r], t[2 * pc + 1][r]);
        xn[((size_t)(p0 + r) * CIN + c0) / 2 + pc] = v;
    }
}

// ================= K0: weight prep (both GEMMs) =================
__global__ void k_wprep(const float* __restrict__ w_off,
                        const float* __restrict__ weight) {
    int i = blockIdx.x * 256 + threadIdx.x;
    if (i < 32 * 2304) {
        int k = i % 2304, o = i / 2304;
        float v = 0.0f;
        if (o < 27) {
            int tap = k / 256, c = k % 256;
            v = w_off[(size_t)(o * 256 + c) * 9 + tap];
        }
        g_w3[i] = __float2bfloat16(v);
    } else {
        int j = i - 32 * 2304;
        if (j < 65536) g_wproj[j] = __float2bfloat16(weight[j]);
    }
}

// ================= K2: offset conv, implicit-GEMM bf16 mma ==================
// One block = one image row (128 px). Double-buffered, 1 barrier/chunk.
__global__ __launch_bounds__(256) void k_offmma(const float* __restrict__ b_off) {
    __shared__ __nv_bfloat16 sA[2][32 * LDK];
    __shared__ __nv_bfloat16 sB[2][128 * LDK];
    int bid = blockIdx.x;               // 0..255
    int b = bid >> 7, y = bid & 127;
    int tid = threadIdx.x;
    int warp = tid >> 5, lane = tid & 31;
    int g = lane >> 2, tg = lane & 3;

    float acc[4][4] = {};

    int sxx = tid >> 1;                 // B stage: pixel x (0..127)
    int scc = (tid & 1) * 16;           // B stage: channel sub-offset
    int sm  = tid >> 3;                 // A stage: row (0..31)
    int skk = (tid & 7) * 4;            // A stage: k sub-offset

    uint2 ra;
    float4 rb0, rb1;
    auto load = [&](int chunk) {
        int tap = chunk >> 3;
        int c0  = (chunk & 7) * 32;
        int k0  = tap * 256 + c0;
        ra = *(const uint2*)(g_w3 + (size_t)sm * 2304 + k0 + skk);
        int yy = y + tap / 3 - 1;
        int sx = sxx + tap % 3 - 1;
        rb0 = make_float4(0.f, 0.f, 0.f, 0.f);
        rb1 = rb0;
        if (yy >= 0 && yy < HH && sx >= 0 && sx < WW) {
            const float4* src = (const float4*)(g_xb +
                ((size_t)((b << 14) + yy * WW + sx) * CIN + c0 + scc));
            rb0 = src[0];
            rb1 = src[1];
        }
    };
    auto store = [&](int buf) {
        *(uint2*)&sA[buf][sm * LDK + skk]       = ra;
        *(float4*)&sB[buf][sxx * LDK + scc]     = rb0;
        *(float4*)&sB[buf][sxx * LDK + scc + 8] = rb1;
    };

    load(0);
    store(0);
    __syncthreads();

    int n0 = warp * 16;
    for (int c = 0; c < 72; ++c) {
        int buf = c & 1;
        if (c < 71) load(c + 1);
#pragma unroll
        for (int ks = 0; ks < 2; ++ks) {
            int kk = ks * 16;
            uint32_t a[2][4];
#pragma unroll
            for (int mt = 0; mt < 2; ++mt) {
                int m = mt * 16;
                a[mt][0] = *(uint32_t*)&sA[buf][(m + g) * LDK + kk + tg * 2];
                a[mt][1] = *(uint32_t*)&sA[buf][(m + g + 8) * LDK + kk + tg * 2];
                a[mt][2] = *(uint32_t*)&sA[buf][(m + g) * LDK + kk + tg * 2 + 8];
                a[mt][3] = *(uint32_t*)&sA[buf][(m + g + 8) * LDK + kk + tg * 2 + 8];
            }
#pragma unroll
            for (int nt = 0; nt < 2; ++nt) {
                int n = n0 + nt * 8;
                uint32_t b0 = *(uint32_t*)&sB[buf][(n + g) * LDK + kk + tg * 2];
                uint32_t b1 = *(uint32_t*)&sB[buf][(n + g) * LDK + kk + tg * 2 + 8];
#pragma unroll
                for (int mt = 0; mt < 2; ++mt)
                    mma16816(acc[mt * 2 + nt], a[mt][0], a[mt][1], a[mt][2],
                             a[mt][3], b0, b1);
            }
        }
        if (c < 71) store(buf ^ 1);
        __syncthreads();
    }

    int p0 = y * WW + warp * 16;
    float* outb = g_tmp + (size_t)b * 27 * HWP;
#pragma unroll
    for (int mt = 0; mt < 2; ++mt)
#pragma unroll
        for (int nt = 0; nt < 2; ++nt) {
            float* c = acc[mt * 2 + nt];
            int col = p0 + nt * 8 + tg * 2;
            int o1 = mt * 16 + g, o2 = o1 + 8;
            if (o1 < 27) {
                float bo = b_off[o1];
                *(float2*)&outb[(size_t)o1 * HWP + col] =
                    make_float2(c[0] + bo, c[1] + bo);
            }
            if (o2 < 27) {
                float bo = b_off[o2];
                *(float2*)&outb[(size_t)o2 * HWP + col] =
                    make_float2(c[2] + bo, c[3] + bo);
            }
        }
}

// ================= K3: stage-1 sum-of-exp per mask plane ====================
__global__ __launch_bounds__(256) void k_sumexp1() {
    int blk = blockIdx.x;               // 0..287
    int bi = blk >> 4, sl = blk & 15;
    const float* plane =
        g_tmp + (size_t)((bi / 9) * 27 + 18 + (bi % 9)) * HWP + sl * 1024;
    __shared__ float red[256];
    int tid = threadIdx.x;
    float s = expf(plane[tid]) + expf(plane[tid + 256]) +
              expf(plane[tid + 512]) + expf(plane[tid + 768]);
    red[tid] = s;
    __syncthreads();
    for (int st = 128; st > 0; st >>= 1) {
        if (tid < st) red[tid] += red[tid + st];
        __syncthreads();
    }
    if (tid == 0) g_part[blk] = red[0];
}

// ================= K4: bilinear gather, flat + HFMA2 accumulation ===========
// Prologue folds sum-exp stage 2. block = 16 pixels, 512 threads;
// 144 threads precompute corners (weights packed bf16x2);
// then 32 threads/pixel, 8 channels each, HFMA2 accumulation (FMA pipe,
// no bf16->fp32 unpack ALU ops -- gather was measured ALU/issue-bound).
__global__ __launch_bounds__(512) void k_gather() {
    __shared__ int      s_off[576];
    __shared__ uint32_t s_w2[576];
    __shared__ float    s_inv[18];
    int base = blockIdx.x * 16;
    int tid = threadIdx.x;

    if (tid < 18) {
        float s = 0.0f;
#pragma unroll
        for (int j = 0; j < 16; ++j) s += g_part[tid * 16 + j];
        s_inv[tid] = 1.0f / s;
    }
    __syncthreads();

    if (tid < 144) {
        int pl = tid / 9, k = tid % 9;
        int n = base + pl;
        int b = n >> 14;
        int p = n & (HWP - 1);
        int y = p >> 7;
        int xx = p & (WW - 1);
        size_t tb = (size_t)b * 27 * HWP + p;
        float dy = g_tmp[tb + (size_t)(2 * k) * HWP];
        float dx = g_tmp[tb + (size_t)(2 * k + 1) * HWP];
        float mv = g_tmp[tb + (size_t)(18 + k) * HWP];
        float m  = expf(mv) * s_inv[b * 9 + k];
        float py = dy + (float)(k / 3 - 1 + y);
        float px = dx + (float)(k % 3 - 1 + xx);
        float fy = floorf(py), fx = floorf(px);
        int iy = (int)fy, ix = (int)fx;
        float ly = py - fy, lx = px - fx;
        float w[4];
        w[0] = (1.0f - ly) * (1.0f - lx) * m;
        w[1] = (1.0f - ly) * lx * m;
        w[2] = ly * (1.0f - lx) * m;
        w[3] = ly * lx * m;
        int idx = tid * 4;
#pragma unroll
        for (int j = 0; j < 4; ++j) {
            int yc = iy + (j >> 1);
            int xc = ix + (j & 1);
            bool v = (yc >= 0) && (yc < HH) && (xc >= 0) && (xc < WW);
            s_off[idx + j] = v ? (int)(((b << 14) + yc * WW + xc) * CIN) : -1;
            __nv_bfloat162 h = __float2bfloat162_rn(w[j]);
            s_w2[idx + j] = *(uint32_t*)&h;
        }
    }
    __syncthreads();

    int pl = tid >> 5;
    int c8 = (tid & 31) * 8;
    __nv_bfloat162 z = __float2bfloat162_rn(0.0f);
    __nv_bfloat162 acc[4] = {z, z, z, z};
    int sb = pl * 36;
#pragma unroll
    for (int t = 0; t < 36; ++t) {
        int off = s_off[sb + t];
        if (off >= 0) {
            uint32_t wb = s_w2[sb + t];
            __nv_bfloat162 w2 = *(__nv_bfloat162*)&wb;
            float4 raw = *(const float4*)(g_xb + off + c8);
            __nv_bfloat162* h = (__nv_bfloat162*)&raw;
#pragma unroll
            for (int q = 0; q < 4; ++q) acc[q] = __hfma2(h[q], w2, acc[q]);
        }
    }
    int n = base + pl;
    *(float4*)(g_agg + (size_t)n * CIN + c8) = *(float4*)acc;
}

// ================= K5: 1x1 projection GEMM (bf16 mma) + bias, pipelined =====
__global__ __launch_bounds__(256) void k_projmma(const float* __restrict__ bias,
                                                 float* __restrict__ out) {
    __shared__ __nv_bfloat16 sA[2][128 * LDK];
    __shared__ __nv_bfloat16 sB[2][128 * LDK];
    int m0 = blockIdx.y * 128;
    int n0 = blockIdx.x * 128;
    int tid = threadIdx.x;
    int warp = tid >> 5, lane = tid & 31;
    int g = lane >> 2, tg = lane & 3;
    int wm = (warp >> 1) * 32;
    int wn = (warp & 1) * 64;

    float acc[2][8][4] = {};

    int sr = tid >> 1;
    int sk = (tid & 1) * 16;

    float4 ra0, ra1, rb0, rb1;
    auto load = [&](int chunk) {
        int k0 = chunk * 32;
        const float4* srcA =
            (const float4*)(g_wproj + (size_t)(m0 + sr) * 256 + k0 + sk);
        ra0 = srcA[0];
        ra1 = srcA[1];
        const float4* srcB =
            (const float4*)(g_agg + (size_t)(n0 + sr) * 256 + k0 + sk);
        rb0 = srcB[0];
        rb1 = srcB[1];
    };
    auto store = [&](int buf) {
        *(float4*)&sA[buf][sr * LDK + sk]     = ra0;
        *(float4*)&sA[buf][sr * LDK + sk + 8] = ra1;
        *(float4*)&sB[buf][sr * LDK + sk]     = rb0;
        *(float4*)&sB[buf][sr * LDK + sk + 8] = rb1;
    };

    load(0);
    store(0);
    __syncthreads();

    for (int c = 0; c < 8; ++c) {
        int buf = c & 1;
        if (c < 7) load(c + 1);
#pragma unroll
        for (int ks = 0; ks < 2; ++ks) {
            int kk = ks * 16;
            uint32_t a[2][4];
#pragma unroll
            for (int mt = 0; mt < 2; ++mt) {
                int m = wm + mt * 16;
                a[mt][0] = *(uint32_t*)&sA[buf][(m + g) * LDK + kk + tg * 2];
                a[mt][1] = *(uint32_t*)&sA[buf][(m + g + 8) * LDK + kk + tg * 2];
                a[mt][2] = *(uint32_t*)&sA[buf][(m + g) * LDK + kk + tg * 2 + 8];
                a[mt][3] = *(uint32_t*)&sA[buf][(m + g + 8) * LDK + kk + tg * 2 + 8];
            }
#pragma unroll
            for (int nt = 0; nt < 8; ++nt) {
                int n = wn + nt * 8;
                uint32_t b0 = *(uint32_t*)&sB[buf][(n + g) * LDK + kk + tg * 2];
                uint32_t b1 = *(uint32_t*)&sB[buf][(n + g) * LDK + kk + tg * 2 + 8];
#pragma unroll
                for (int mt = 0; mt < 2; ++mt)
                    mma16816(acc[mt][nt], a[mt][0], a[mt][1], a[mt][2], a[mt][3],
                             b0, b1);
            }
        }
        if (c < 7) store(buf ^ 1);
        __syncthreads();
    }

    int b = n0 >> 14;
    int p0 = (n0 & (HWP - 1)) + wn;
#pragma unroll
    for (int mt = 0; mt < 2; ++mt) {
        int o1 = m0 + wm + mt * 16 + g;
        int o2 = o1 + 8;
        float bo1 = bias[o1], bo2 = bias[o2];
        float* r1 = out + (size_t)(b * OCH + o1) * HWP + p0;
        float* r2 = out + (size_t)(b * OCH + o2) * HWP + p0;
#pragma unroll
        for (int nt = 0; nt < 8; ++nt) {
            float* c = acc[mt][nt];
            int col = nt * 8 + tg * 2;
            *(float2*)&r1[col] = make_float2(c[0] + bo1, c[1] + bo1);
            *(float2*)&r2[col] = make_float2(c[2] + bo2, c[3] + bo2);
        }
    }
}

// ================= launch =================
// 7 launches; profiled slot (4th launch) = k_offmma this round.
extern "C" void kernel_launch(void* const* d_in, const int* in_sizes, int n_in,
                              void* d_out, int out_size) {
    const float* x      = (const float*)d_in[0];
    const float* w_off  = (const float*)d_in[1];
    const float* b_off  = (const float*)d_in[2];
    const float* weight = (const float*)d_in[3];
    const float* bias   = (const float*)d_in[4];
    float* out = (float*)d_out;

    k_transpose<<<dim3(HWP / 32, CIN / 32), dim3(32, 8)>>>(x, 0);
    k_transpose<<<dim3(HWP / 32, CIN / 32), dim3(32, 8)>>>(x, 1);
    k_wprep<<<544, 256>>>(w_off, weight);
    k_offmma<<<256, 256>>>(b_off);
    k_sumexp1<<<288, 256>>>();
    k_gather<<<NPIX / 16, 512>>>();
    k_projmma<<<dim3(NPIX / 128, OCH / 128), 256>>>(bias, out);
}